// round 8
// baseline (speedup 1.0000x reference)
#include <cuda_runtime.h>
#include <cstdint>

// Problem constants
static constexpr int BB = 32;    // batch
static constexpr int TT = 512;   // time
static constexpr int HH = 1024;  // hidden
static constexpr int GG = 4096;  // 4*H gate columns (order i,f,g,o)
static constexpr int NL = 2;     // layers

static constexpr int NBLK = 128; // persistent blocks (8 hidden units each)
static constexpr int NTHR = 256; // 8 warps (8-way K-split)
static constexpr int SMEM_SEQ = 131072 + 32768 + 32768; // Wh 128K + Hs2 32K + Pz 32K

// ---------------------------------------------------------------------------
// Device scratch (static __device__ arrays: allocation-free per harness rules)
// ---------------------------------------------------------------------------
__device__ float g_zx[(size_t)TT * GG * BB];   // [t][c][b]  input-GEMM result
__device__ float g_y0[(size_t)TT * HH * BB];   // layer-0 output, [t][u][b]
__device__ float g_h[2][HH * BB];              // h double buffer, [u][b]
__device__ unsigned g_bar;                     // grid-barrier arrival counter

using u64 = unsigned long long;

// Packed fp32x2 FMA (Blackwell FFMA2 — only reachable via PTX)
__device__ __forceinline__ void ffma2(u64& d, u64 a, u64 b) {
    asm("fma.rn.f32x2 %0, %1, %2, %0;" : "+l"(d) : "l"(a), "l"(b));
}
__device__ __forceinline__ float2 f2(u64 v) {
    float2 r;
    r.x = __uint_as_float((unsigned)(v & 0xffffffffu));
    r.y = __uint_as_float((unsigned)(v >> 32));
    return r;
}
__device__ __forceinline__ float sigmoidf_(float x) {
    return 1.0f / (1.0f + __expf(-x));
}

// ---------------------------------------------------------------------------
// Reset recurrent state + barrier counter (runs before each layer)
// ---------------------------------------------------------------------------
__global__ void zero_state() {
    int i = blockIdx.x * blockDim.x + threadIdx.x;
    if (i == 0) g_bar = 0u;
    if (i < HH * BB) {
        g_h[0][i] = 0.0f;
        g_h[1][i] = 0.0f;
    }
}

// ---------------------------------------------------------------------------
// Input GEMM:  Zx[t][c][b] = sum_k X[.,t,k] * W[k,c] + bias[c]
// MODE 0: X external input [B][T][H];  MODE 1: X = g_y0 [T][H][B]
//
// Grid (16 col-tiles of 256, T). Block 256 = 8 warps; warp owns 32 cols.
// f32x2 pairs span COLUMNS (natural u64/LDS.128 from plain W rows).
// X duplicated in smem (rows padded to 33 float2 -> conflict-free staging in
// both modes). Thread batch tile b = i*8+bg -> conflict-free LDS.64.
// DOUBLE-BUFFERED staging: next chunk's LDGs issue before the current 16x16
// FFMA2 block, STS after it, one __syncthreads per chunk. L2 latency hides
// under ~640 cyc of compute; barrier count halves.
// ---------------------------------------------------------------------------
template <int MODE>
__global__ __launch_bounds__(256) void gemm_zx(const float* __restrict__ X,
                                               const float* __restrict__ W,
                                               const float* __restrict__ bias) {
    __shared__ alignas(16) float2 Xs2[2][16][33];  // [buf][kk][b] dup, padded
    __shared__ alignas(16) float  Ws[2][16][256];  // [buf][kk][c] plain

    const int ct   = blockIdx.x;          // cols [ct*256, ct*256+256)
    const int t    = blockIdx.y;
    const int tid  = threadIdx.x;
    const int warp = tid >> 5;
    const int lane = tid & 31;
    const int bg   = lane >> 2;           // 0..7 batch group
    const int cg   = lane & 3;            // 0..3 col-pair group (4 pairs = 8 cols)

    u64 acc[4][4];                        // [i: b=i*8+bg][j: colpair cg*4+j]
#pragma unroll
    for (int i = 0; i < 4; i++)
#pragma unroll
        for (int j = 0; j < 4; j++) acc[i][j] = 0ull;

    // ---- prologue: stage chunk 0 directly into buffer 0 ----
    {
        const int k0 = 0;
#pragma unroll
        for (int r = 0; r < 2; r++) {
            int id = tid + r * 256;
            float v; int kk, bb;
            if (MODE == 0) { kk = id & 15; bb = id >> 4;
                v = X[((size_t)bb * TT + t) * HH + k0 + kk]; }
            else           { bb = id & 31; kk = id >> 5;
                v = g_y0[((size_t)t * HH + k0 + kk) * BB + bb]; }
            Xs2[0][kk][bb] = make_float2(v, v);
        }
#pragma unroll
        for (int r = 0; r < 4; r++) {
            int idx = tid + r * 256;
            int row = idx >> 6, cv = idx & 63;
            reinterpret_cast<float4*>(Ws[0][row])[cv] =
                reinterpret_cast<const float4*>(W + (size_t)(k0 + row) * GG + ct * 256)[cv];
        }
    }
    __syncthreads();

    for (int c = 0; c < 64; c++) {
        const int cur = c & 1;
        const bool havenext = (c < 63);

        // ---- issue next chunk's loads into registers (latency overlaps
        //      the compute block below) ----
        float  xpre[2];
        float4 wpre[4];
        if (havenext) {
            const int k1 = (c + 1) * 16;
#pragma unroll
            for (int r = 0; r < 2; r++) {
                int id = tid + r * 256;
                if (MODE == 0) { int kk = id & 15, bb = id >> 4;
                    xpre[r] = X[((size_t)bb * TT + t) * HH + k1 + kk]; }
                else           { int bb = id & 31, kk = id >> 5;
                    xpre[r] = g_y0[((size_t)t * HH + k1 + kk) * BB + bb]; }
            }
#pragma unroll
            for (int r = 0; r < 4; r++) {
                int idx = tid + r * 256;
                int row = idx >> 6, cv = idx & 63;
                wpre[r] = reinterpret_cast<const float4*>(
                    W + (size_t)(k1 + row) * GG + ct * 256)[cv];
            }
        }

        // ---- compute 16x16 FFMA2 block from current buffer ----
#pragma unroll
        for (int kk = 0; kk < 16; kk++) {
            const u64*       hr = reinterpret_cast<const u64*>(Xs2[cur][kk]);
            const longlong2* wr = reinterpret_cast<const longlong2*>(&Ws[cur][kk][warp * 32]);
            u64 hh[4], ww[4];
#pragma unroll
            for (int i = 0; i < 4; i++) hh[i] = hr[i * 8 + bg];
            longlong2 wa = wr[cg * 2], wb = wr[cg * 2 + 1];
            ww[0] = (u64)wa.x; ww[1] = (u64)wa.y;
            ww[2] = (u64)wb.x; ww[3] = (u64)wb.y;
#pragma unroll
            for (int i = 0; i < 4; i++)
#pragma unroll
                for (int j = 0; j < 4; j++) ffma2(acc[i][j], hh[i], ww[j]);
        }

        // ---- commit prefetched registers to the other buffer ----
        if (havenext) {
            const int nxt = cur ^ 1;
#pragma unroll
            for (int r = 0; r < 2; r++) {
                int id = tid + r * 256;
                int kk, bb;
                if (MODE == 0) { kk = id & 15; bb = id >> 4; }
                else           { bb = id & 31; kk = id >> 5; }
                Xs2[nxt][kk][bb] = make_float2(xpre[r], xpre[r]);
            }
#pragma unroll
            for (int r = 0; r < 4; r++) {
                int idx = tid + r * 256;
                int row = idx >> 6, cv = idx & 63;
                reinterpret_cast<float4*>(Ws[nxt][row])[cv] = wpre[r];
            }
        }
        // single barrier per chunk: guarantees (a) this chunk's compute done
        // on buffer 'cur' before it is overwritten next iteration, (b) the
        // freshly staged buffer is visible to all warps.
        __syncthreads();
    }

    // epilogue: Zx[t][c][b] = acc + bias[c].  Streaming stores: Zx is a
    // 256 MB write-once stream; keep it from thrashing L2 (Wx/Wh resident).
#pragma unroll
    for (int j = 0; j < 4; j++) {
        int   c0 = ct * 256 + warp * 32 + (cg * 4 + j) * 2;
        float b0 = bias[c0], b1 = bias[c0 + 1];
#pragma unroll
        for (int i = 0; i < 4; i++) {
            int    b = i * 8 + bg;
            float2 v = f2(acc[i][j]);
            __stcs(&g_zx[((size_t)t * GG + c0) * BB + b],     v.x + b0);
            __stcs(&g_zx[((size_t)t * GG + c0 + 1) * BB + b], v.y + b1);
        }
    }
}

// ---------------------------------------------------------------------------
// Persistent recurrence kernel: one launch runs all T=512 steps of one layer.
//
// 128 blocks (8 hidden units each; 1 block/SM, 128 < #SMs -> all co-resident,
// software grid barrier is safe). Block = 8 warps = 8-way K-split (128 k's
// each). Wh slice [1024][32] resident in smem (loaded once, vectorized).
// h chunk staging is software-pipelined (register prefetch); Zx addends
// prefetched at step start. c lives in a register for the entire launch.
// Split-arrive barrier: arrive right after the g_h store+fence, y-output
// stores overlap other blocks' arrival skew, then wait.
// h read via __ldcg (L2), so cross-SM staleness is impossible.
// YMODE 0: y -> g_y0[t][u][b] ; YMODE 1: y -> yout[b][t][u]
// ---------------------------------------------------------------------------
template <int YMODE>
__global__ __launch_bounds__(NTHR, 1) void lstm_seq(const float* __restrict__ Wh,
                                                    float* __restrict__ yout,
                                                    float* __restrict__ hfin,
                                                    float* __restrict__ cfin) {
    extern __shared__ char smem_raw[];
    float*  Wh_s = reinterpret_cast<float*>(smem_raw);                   // [1024][32]
    float2* Hs2  = reinterpret_cast<float2*>(smem_raw + 131072);         // [8][16][32]
    float*  Pz   = reinterpret_cast<float*>(smem_raw + 131072 + 32768);  // [8][32][32]

    const int u0   = blockIdx.x * 8;
    const int tid  = threadIdx.x;
    const int ks   = tid >> 5;            // warp = K-split index (0..7)
    const int lane = tid & 31;
    const int bg   = lane >> 2;           // 0..7
    const int cg   = lane & 3;            // 0..3

    // Load resident Wh slice (one-time): Wh_s[k*32 + cl], cl = g*8 + uu.
    // Vectorized: thread loads float4 = 4 consecutive units of one gate row.
    // 1024 k * 4 gates * 2 float4-chunks = 8192 float4 slots, 32 per thread.
    for (int s = tid; s < 8192; s += NTHR) {
        int k = s >> 3;                  // 0..1023
        int gq = s & 7;                  // gate*2 + quad
        int g = gq >> 1, q = gq & 1;     // q: which half of 8 units
        float4 w4 = *reinterpret_cast<const float4*>(
            Wh + (size_t)k * GG + g * HH + u0 + q * 4);
        int cl = g * 8 + q * 4;
        float* dst = Wh_s + k * 32 + cl;
        dst[0] = w4.x; dst[1] = w4.y; dst[2] = w4.z; dst[3] = w4.w;
    }
    __syncthreads();

    float2* myH = Hs2 + ks * (16 * 32);
    float*  myP = Pz  + ks * (32 * 32);

    // epilogue identity of this thread (also owner of c_reg)
    const int uu = ks;
    const int b  = lane;
    const int u  = u0 + uu;
    float c_reg = 0.0f;

    const int kbeg = ks * 128;

    for (int t = 0; t < TT; t++) {
        const float* __restrict__ hin = g_h[t & 1];

        // prefetch Zx addends for this step (independent of barrier; hides
        // DRAM latency under the whole mainloop). Streaming: read-once data.
        float zadd[4];
#pragma unroll
        for (int g = 0; g < 4; g++)
            zadd[g] = __ldcs(&g_zx[((size_t)t * GG + g * HH + u) * BB + b]);

        u64 acc[4][4];
#pragma unroll
        for (int i = 0; i < 4; i++)
#pragma unroll
            for (int j = 0; j < 4; j++) acc[i][j] = 0ull;

        // prologue: prefetch chunk 0 of h into registers
        float pre[16];
#pragma unroll
        for (int r = 0; r < 16; r++)
            pre[r] = __ldcg(&hin[(kbeg + r) * BB + lane]);

        for (int c8 = 0; c8 < 8; c8++) {
            const int k0 = kbeg + c8 * 16;
            // commit prefetched h chunk to smem (duplicated for f32x2)
#pragma unroll
            for (int r = 0; r < 16; r++)
                myH[r * 32 + lane] = make_float2(pre[r], pre[r]);
            __syncwarp();
            // prefetch next chunk while computing this one
            if (c8 < 7) {
#pragma unroll
                for (int r = 0; r < 16; r++)
                    pre[r] = __ldcg(&hin[(k0 + 16 + r) * BB + lane]);
            }

#pragma unroll
            for (int kk = 0; kk < 16; kk++) {
                const u64*       hr = reinterpret_cast<const u64*>(myH + kk * 32);
                const longlong2* wr = reinterpret_cast<const longlong2*>(Wh_s + (k0 + kk) * 32);
                u64 hh[4], ww[4];
#pragma unroll
                for (int i = 0; i < 4; i++) hh[i] = hr[i * 8 + bg];
                longlong2 wa = wr[cg * 2], wb = wr[cg * 2 + 1];
                ww[0] = (u64)wa.x; ww[1] = (u64)wa.y;
                ww[2] = (u64)wb.x; ww[3] = (u64)wb.y;
#pragma unroll
                for (int i = 0; i < 4; i++)
#pragma unroll
                    for (int j = 0; j < 4; j++) ffma2(acc[i][j], hh[i], ww[j]);
            }
            __syncwarp();
        }

        // dump partials: Pz[ks][cl][b]
#pragma unroll
        for (int j = 0; j < 4; j++) {
            int cl0 = (cg * 4 + j) * 2;
#pragma unroll
            for (int i = 0; i < 4; i++) {
                int    bb = i * 8 + bg;
                float2 v  = f2(acc[i][j]);
                myP[cl0 * 32 + bb]       = v.x;
                myP[(cl0 + 1) * 32 + bb] = v.y;
            }
        }
        __syncthreads();

        // fused gate epilogue: thread -> (uu, b); 256 = 8u x 32b
        float h_new;
        {
            float z[4];
#pragma unroll
            for (int g = 0; g < 4; g++) {
                int   cl = g * 8 + uu;
                float s  = zadd[g];
#pragma unroll
                for (int w = 0; w < 8; w++) s += Pz[w * 1024 + cl * 32 + b];
                z[g] = s;
            }
            float gi = sigmoidf_(z[0]);
            float gf = sigmoidf_(z[1]);
            float gc = tanhf(z[2]);
            float go = sigmoidf_(z[3]);
            c_reg = gf * c_reg + gi * gc;
            h_new = go * tanhf(c_reg);

            // the ONLY cross-block dependency: publish h first
            g_h[(t + 1) & 1][u * BB + b] = h_new;
        }

        // --- split-arrive grid barrier ---
        __threadfence();           // h store visible device-wide
        __syncthreads();           // whole block done publishing
        if (tid == 0) atomicAdd(&g_bar, 1u);   // ARRIVE early

        // y-output stores overlap other blocks' arrival skew (no intra-
        // kernel reader; g_y0 is consumed by a later launch)
        if (YMODE == 0) {
            __stcs(&g_y0[((size_t)t * HH + u) * BB + b], h_new);  // [T][H][B]
        } else {
            __stcs(&yout[((size_t)b * TT + t) * HH + u], h_new);  // [B][T][H]
        }
        if (t == TT - 1) {
            hfin[b * HH + u] = h_new;
            cfin[b * HH + u] = c_reg;
        }

        if (tid == 0) {            // WAIT
            const unsigned target = (unsigned)(t + 1) * (unsigned)NBLK;
            while (*((volatile unsigned*)&g_bar) < target) { }
            __threadfence();       // acquire: new h visible before next step
        }
        __syncthreads();
    }
}

// ---------------------------------------------------------------------------
// Host launcher (graph-capturable: 6 kernel launches total)
// ---------------------------------------------------------------------------
extern "C" void kernel_launch(void* const* d_in, const int* in_sizes, int n_in,
                              void* d_out, int out_size) {
    const float* x    = (const float*)d_in[0];   // [B,T,H]
    const float* Wx   = (const float*)d_in[1];   // [L,H,4H]
    const float* Wh   = (const float*)d_in[2];   // [L,H,4H]
    const float* bias = (const float*)d_in[3];   // [L,4H]

    float* out = (float*)d_out;
    float* y   = out;                               // [B,T,H]
    float* hf  = out + (size_t)BB * TT * HH;        // [L,B,H]
    float* cf  = hf + (size_t)NL * BB * HH;         // [L,B,H]

    const size_t wl = (size_t)HH * GG;              // per-layer weight stride

    cudaFuncSetAttribute(lstm_seq<0>, cudaFuncAttributeMaxDynamicSharedMemorySize, SMEM_SEQ);
    cudaFuncSetAttribute(lstm_seq<1>, cudaFuncAttributeMaxDynamicSharedMemorySize, SMEM_SEQ);

    // ---- Layer 0 ----
    zero_state<<<128, 256>>>();
    gemm_zx<0><<<dim3(16, TT), 256>>>(x, Wx, bias);
    lstm_seq<0><<<NBLK, NTHR, SMEM_SEQ>>>(Wh, nullptr, hf, cf);

    // ---- Layer 1 ----
    zero_state<<<128, 256>>>();
    gemm_zx<1><<<dim3(16, TT), 256>>>(nullptr, Wx + wl, bias + GG);
    lstm_seq<1><<<NBLK, NTHR, SMEM_SEQ>>>(Wh + wl, y, hf + BB * HH, cf + BB * HH);
}

// round 11
// speedup vs baseline: 1.2394x; 1.2394x over previous
#include <cuda_runtime.h>
#include <cuda_bf16.h>
#include <cstdint>

// Problem constants
static constexpr int BB = 32;    // batch
static constexpr int TT = 512;   // time
static constexpr int HH = 1024;  // hidden
static constexpr int GG = 4096;  // 4*H gate columns (order i,f,g,o)
static constexpr int NL = 2;     // layers

static constexpr int NBLK = 128; // persistent blocks for recurrence
static constexpr int NTHR = 256;
static constexpr int SMEM_SEQ = 131072 + 32768 + 32768;

using u64 = unsigned long long;

// ---------------------------------------------------------------------------
// Device scratch
// ---------------------------------------------------------------------------
__device__ float g_zx[(size_t)TT * GG * BB];   // [t][c][b] input-GEMM result
__device__ float g_y0[(size_t)TT * HH * BB];   // layer-0 h, [t][u][b]
__device__ float g_h[2][HH * BB];              // h double buffer, [u][b]
__device__ unsigned g_bar;                     // grid barrier counter

// bf16 split operands for MMA GEMM phases
__device__ __align__(16) __nv_bfloat16 g_xh[(size_t)BB * TT * HH];   // [b][t][k]
__device__ __align__(16) __nv_bfloat16 g_xl[(size_t)BB * TT * HH];
__device__ __align__(16) __nv_bfloat16 g_y0h[(size_t)TT * BB * HH];  // [(t,b)][k]
__device__ __align__(16) __nv_bfloat16 g_y0l[(size_t)TT * BB * HH];
__device__ __align__(16) __nv_bfloat16 g_wth[(size_t)NL * GG * HH];  // W^T [l][c][k]
__device__ __align__(16) __nv_bfloat16 g_wtl[(size_t)NL * GG * HH];

// ---------------------------------------------------------------------------
// Helpers (all baseline PTX features; no sm_103a-only instructions)
// ---------------------------------------------------------------------------
__device__ __forceinline__ uint32_t smem_to_u32(const void* p) {
    uint32_t a;
    asm("{ .reg .u64 t; cvta.to.shared.u64 t, %1; cvt.u32.u64 %0, t; }"
        : "=r"(a) : "l"(p));
    return a;
}

#define LDSM_X4(r0, r1, r2, r3, a) \
    asm volatile("ldmatrix.sync.aligned.m8n8.x4.shared.b16 {%0,%1,%2,%3}, [%4];" \
                 : "=r"(r0), "=r"(r1), "=r"(r2), "=r"(r3) : "r"(a))

#define MMA16816(d, a0, a1, a2, a3, b0, b1) \
    asm volatile("mma.sync.aligned.m16n8k16.row.col.f32.bf16.bf16.f32 " \
                 "{%0,%1,%2,%3}, {%4,%5,%6,%7}, {%8,%9}, {%0,%1,%2,%3};" \
                 : "+f"((d)[0]), "+f"((d)[1]), "+f"((d)[2]), "+f"((d)[3]) \
                 : "r"(a0), "r"(a1), "r"(a2), "r"(a3), "r"(b0), "r"(b1))

// fp32 -> bf16 hi/lo split
__device__ __forceinline__ void bf16split(float v, __nv_bfloat16& hi, __nv_bfloat16& lo) {
    hi = __float2bfloat16(v);
    lo = __float2bfloat16(v - __bfloat162float(hi));
}

__device__ __forceinline__ void ffma2(u64& d, u64 a, u64 b) {
    asm("fma.rn.f32x2 %0, %1, %2, %0;" : "+l"(d) : "l"(a), "l"(b));
}
__device__ __forceinline__ float2 f2(u64 v) {
    float2 r;
    r.x = __uint_as_float((unsigned)(v & 0xffffffffu));
    r.y = __uint_as_float((unsigned)(v >> 32));
    return r;
}
__device__ __forceinline__ float sigmoidf_(float x) {
    return 1.0f / (1.0f + __expf(-x));
}

// ---------------------------------------------------------------------------
// Reset recurrent state + barrier counter
// ---------------------------------------------------------------------------
__global__ void zero_state() {
    int i = blockIdx.x * blockDim.x + threadIdx.x;
    if (i == 0) g_bar = 0u;
    if (i < HH * BB) {
        g_h[0][i] = 0.0f;
        g_h[1][i] = 0.0f;
    }
}

// ---------------------------------------------------------------------------
// Prep: Wx[l][k][c] fp32  ->  W^T hi/lo bf16 [l][c][k]   (32x32 smem transpose)
// ---------------------------------------------------------------------------
__global__ __launch_bounds__(256) void conv_w(const float* __restrict__ Wx) {
    __shared__ float tile[32][33];
    const int l = blockIdx.z, c0 = blockIdx.x * 32, k0 = blockIdx.y * 32;
    const int tx = threadIdx.x & 31, ty = threadIdx.x >> 5;
    const float* W = Wx + (size_t)l * HH * GG;
#pragma unroll
    for (int i = 0; i < 4; i++)
        tile[ty + i * 8][tx] = W[(size_t)(k0 + ty + i * 8) * GG + c0 + tx];
    __syncthreads();
#pragma unroll
    for (int i = 0; i < 4; i++) {
        int c = ty + i * 8;
        __nv_bfloat16 hi, lo;
        bf16split(tile[tx][c], hi, lo);
        size_t off = (size_t)l * GG * HH + (size_t)(c0 + c) * HH + k0 + tx;
        g_wth[off] = hi;
        g_wtl[off] = lo;
    }
}

// ---------------------------------------------------------------------------
// Prep: x fp32 [b][t][k] -> g_xh/g_xl bf16 same layout
// ---------------------------------------------------------------------------
__global__ __launch_bounds__(256) void conv_x(const float* __restrict__ x) {
    size_t i = ((size_t)blockIdx.x * 256 + threadIdx.x) * 4;
    float4 v = *reinterpret_cast<const float4*>(x + i);
    __nv_bfloat16 h[4], l[4];
    bf16split(v.x, h[0], l[0]); bf16split(v.y, h[1], l[1]);
    bf16split(v.z, h[2], l[2]); bf16split(v.w, h[3], l[3]);
    uint2 hw, lw;
    hw.x = (unsigned)__bfloat16_as_ushort(h[0]) | ((unsigned)__bfloat16_as_ushort(h[1]) << 16);
    hw.y = (unsigned)__bfloat16_as_ushort(h[2]) | ((unsigned)__bfloat16_as_ushort(h[3]) << 16);
    lw.x = (unsigned)__bfloat16_as_ushort(l[0]) | ((unsigned)__bfloat16_as_ushort(l[1]) << 16);
    lw.y = (unsigned)__bfloat16_as_ushort(l[2]) | ((unsigned)__bfloat16_as_ushort(l[3]) << 16);
    *reinterpret_cast<uint2*>(&g_xh[i]) = hw;
    *reinterpret_cast<uint2*>(&g_xl[i]) = lw;
}

// ---------------------------------------------------------------------------
// Prep: g_y0 fp32 [t][u][b] -> g_y0h/l bf16 [(t*32+b)][u]
// ---------------------------------------------------------------------------
__global__ __launch_bounds__(256) void conv_y0() {
    __shared__ float s[128][33];
    const int t = blockIdx.x, u0 = blockIdx.y * 128;
    const int lane = threadIdx.x & 31, w = threadIdx.x >> 5;
#pragma unroll
    for (int i = 0; i < 16; i++) {
        int uu = w + i * 8;
        s[uu][lane] = g_y0[((size_t)t * HH + u0 + uu) * BB + lane];
    }
    __syncthreads();
#pragma unroll
    for (int j = 0; j < 4; j++) {
        int b = w + j * 8;
        size_t base = ((size_t)(t * BB + b)) * HH + u0;
#pragma unroll
        for (int i = 0; i < 4; i++) {
            int uu = lane + i * 32;
            __nv_bfloat16 hi, lo;
            bf16split(s[uu][b], hi, lo);
            g_y0h[base + uu] = hi;
            g_y0l[base + uu] = lo;
        }
    }
}

// ---------------------------------------------------------------------------
// MMA GEMM: Zx[(t,b), c] = A[16384,1024] @ W[1024,4096] + bias, split-bf16
// via warp-level mma.sync m16n8k16 (3 passes, fp32 accumulate in registers).
//
// Grid (GG/128 = 32 n-tiles, 16384/128 = 128 m-tiles), block 256 = 8 warps.
// Warp grid 4(m) x 2(n): warp tile 32(m) x 64(n). K-chunks of 32.
// SMEM tiles [128 rows][40 bf16] (pad 40 -> ldmatrix rows hit distinct banks).
// A tile row r <-> (t = t0 + r/32, b = r%32).
// ---------------------------------------------------------------------------
template <int LAYER>
__global__ __launch_bounds__(256) void gemm_mma(const float* __restrict__ bias) {
    __shared__ __align__(16) __nv_bfloat16 Ah_s[128 * 40];
    __shared__ __align__(16) __nv_bfloat16 Al_s[128 * 40];
    __shared__ __align__(16) __nv_bfloat16 Bh_s[128 * 40];
    __shared__ __align__(16) __nv_bfloat16 Bl_s[128 * 40];

    const int tid  = threadIdx.x;
    const int wid  = tid >> 5;
    const int lane = tid & 31;
    const int wm   = wid & 3;      // m group: rows wm*32..+31
    const int wn   = wid >> 2;     // n group: cols wn*64..+63
    const int n0   = blockIdx.x * 128;
    const int t0   = blockIdx.y * 4;

    // staging coordinates: e = tid + i*256, row = e/4, seg = e%4 (8 bf16 each)
    int srow[2], sseg[2];
    unsigned arow[2], brow[2];
#pragma unroll
    for (int i = 0; i < 2; i++) {
        int e   = tid + i * 256;
        srow[i] = e >> 2;
        sseg[i] = e & 3;
        if (LAYER == 0) {
            int b = srow[i] & 31, t = t0 + (srow[i] >> 5);
            arow[i] = (unsigned)(b * TT + t) * HH;
        } else {
            arow[i] = (unsigned)(blockIdx.y * 128 + srow[i]) * HH;
        }
        brow[i] = (unsigned)(n0 + srow[i]) * HH;
    }
    const __nv_bfloat16* Ah = (LAYER == 0) ? g_xh : g_y0h;
    const __nv_bfloat16* Al = (LAYER == 0) ? g_xl : g_y0l;
    const __nv_bfloat16* Bh = g_wth + (size_t)LAYER * GG * HH;
    const __nv_bfloat16* Bl = g_wtl + (size_t)LAYER * GG * HH;

    // ldmatrix lane addresses (byte offsets within a [128][40]-bf16 tile)
    // A x4: row = base + (lane & 15); col = ks*16 + (lane >= 16 ? 8 : 0)
    const int a_lr = lane & 15;
    const int a_lc = (lane & 16) ? 8 : 0;
    // B x4 (two n-frags): row = nbase + (lane&7) + (lane&16 ? 8 : 0);
    //                     col = ks*16 + (lane&8 ? 8 : 0)
    const int b_lr = (lane & 7) + ((lane & 16) ? 8 : 0);
    const int b_lc = (lane & 8) ? 8 : 0;

    const uint32_t uAh = smem_to_u32(Ah_s), uAl = smem_to_u32(Al_s);
    const uint32_t uBh = smem_to_u32(Bh_s), uBl = smem_to_u32(Bl_s);

    float acc[2][8][4];
#pragma unroll
    for (int fm = 0; fm < 2; fm++)
#pragma unroll
        for (int nf = 0; nf < 8; nf++)
#pragma unroll
            for (int q = 0; q < 4; q++) acc[fm][nf][q] = 0.0f;

    for (int ch = 0; ch < 32; ch++) {
        const int k0 = ch * 32;
        // ---- stage 4 tiles: [128][32] bf16 each, 2 uint4 per thread ----
#pragma unroll
        for (int i = 0; i < 2; i++) {
            const unsigned go = k0 + sseg[i] * 8;
            const unsigned so = srow[i] * 40 + sseg[i] * 8;
            *reinterpret_cast<uint4*>(Ah_s + so) =
                *reinterpret_cast<const uint4*>(Ah + arow[i] + go);
            *reinterpret_cast<uint4*>(Al_s + so) =
                *reinterpret_cast<const uint4*>(Al + arow[i] + go);
            *reinterpret_cast<uint4*>(Bh_s + so) =
                *reinterpret_cast<const uint4*>(Bh + brow[i] + go);
            *reinterpret_cast<uint4*>(Bl_s + so) =
                *reinterpret_cast<const uint4*>(Bl + brow[i] + go);
        }
        __syncthreads();

#pragma unroll
        for (int ks = 0; ks < 2; ks++) {
            // A fragments (hi & lo) for both 16-row m-frags
            uint32_t ah[2][4], al[2][4];
#pragma unroll
            for (int fm = 0; fm < 2; fm++) {
                uint32_t off = (uint32_t)((wm * 32 + fm * 16 + a_lr) * 40 +
                                          ks * 16 + a_lc) * 2;
                LDSM_X4(ah[fm][0], ah[fm][1], ah[fm][2], ah[fm][3], uAh + off);
                LDSM_X4(al[fm][0], al[fm][1], al[fm][2], al[fm][3], uAl + off);
            }
#pragma unroll
            for (int ng = 0; ng < 4; ng++) {
                uint32_t off = (uint32_t)((wn * 64 + ng * 16 + b_lr) * 40 +
                                          ks * 16 + b_lc) * 2;
                uint32_t bh0, bh1, bh2, bh3, bl0, bl1, bl2, bl3;
                LDSM_X4(bh0, bh1, bh2, bh3, uBh + off);
                LDSM_X4(bl0, bl1, bl2, bl3, uBl + off);
                const int nf0 = ng * 2, nf1 = ng * 2 + 1;
#pragma unroll
                for (int fm = 0; fm < 2; fm++) {
                    // hi*hi
                    MMA16816(acc[fm][nf0], ah[fm][0], ah[fm][1], ah[fm][2], ah[fm][3], bh0, bh1);
                    MMA16816(acc[fm][nf1], ah[fm][0], ah[fm][1], ah[fm][2], ah[fm][3], bh2, bh3);
                    // hi*lo
                    MMA16816(acc[fm][nf0], ah[fm][0], ah[fm][1], ah[fm][2], ah[fm][3], bl0, bl1);
                    MMA16816(acc[fm][nf1], ah[fm][0], ah[fm][1], ah[fm][2], ah[fm][3], bl2, bl3);
                    // lo*hi
                    MMA16816(acc[fm][nf0], al[fm][0], al[fm][1], al[fm][2], al[fm][3], bh0, bh1);
                    MMA16816(acc[fm][nf1], al[fm][0], al[fm][1], al[fm][2], al[fm][3], bh2, bh3);
                }
            }
        }
        __syncthreads();
    }

    // ---- epilogue: acc -> g_zx[t][c][b] (+bias). Frag layout:
    // d0:(r=lane/4, c=2*(lane%4))  d1:(r, c+1)  d2:(r+8, c)  d3:(r+8, c+1)
    const int er = lane >> 2, ec = (lane & 3) * 2;
#pragma unroll
    for (int fm = 0; fm < 2; fm++) {
#pragma unroll
        for (int nf = 0; nf < 8; nf++) {
            const int c0 = n0 + wn * 64 + nf * 8 + ec;
            const float bv0 = __ldg(&bias[c0]), bv1 = __ldg(&bias[c0 + 1]);
#pragma unroll
            for (int h = 0; h < 2; h++) {   // h=0: rows r, h=1: rows r+8
                const int r = wm * 32 + fm * 16 + er + h * 8;
                const int t = t0 + (r >> 5), b = r & 31;
                const size_t base = ((size_t)t * GG + c0) * BB + b;
                __stcs(&g_zx[base],       acc[fm][nf][h * 2 + 0] + bv0);
                __stcs(&g_zx[base + BB],  acc[fm][nf][h * 2 + 1] + bv1);
            }
        }
    }
}

// ---------------------------------------------------------------------------
// Persistent recurrence kernel (UNCHANGED from the passing R8 version)
// ---------------------------------------------------------------------------
template <int YMODE>
__global__ __launch_bounds__(NTHR, 1) void lstm_seq(const float* __restrict__ Wh,
                                                    float* __restrict__ yout,
                                                    float* __restrict__ hfin,
                                                    float* __restrict__ cfin) {
    extern __shared__ char smem_raw[];
    float*  Wh_s = reinterpret_cast<float*>(smem_raw);                   // [1024][32]
    float2* Hs2  = reinterpret_cast<float2*>(smem_raw + 131072);         // [8][16][32]
    float*  Pz   = reinterpret_cast<float*>(smem_raw + 131072 + 32768);  // [8][32][32]

    const int u0   = blockIdx.x * 8;
    const int tid  = threadIdx.x;
    const int ks   = tid >> 5;
    const int lane = tid & 31;
    const int bg   = lane >> 2;
    const int cg   = lane & 3;

    for (int s = tid; s < 8192; s += NTHR) {
        int k = s >> 3;
        int gq = s & 7;
        int g = gq >> 1, q = gq & 1;
        float4 w4 = *reinterpret_cast<const float4*>(
            Wh + (size_t)k * GG + g * HH + u0 + q * 4);
        int cl = g * 8 + q * 4;
        float* dst = Wh_s + k * 32 + cl;
        dst[0] = w4.x; dst[1] = w4.y; dst[2] = w4.z; dst[3] = w4.w;
    }
    __syncthreads();

    float2* myH = Hs2 + ks * (16 * 32);
    float*  myP = Pz  + ks * (32 * 32);

    const int uu = ks;
    const int b  = lane;
    const int u  = u0 + uu;
    float c_reg = 0.0f;
    const int kbeg = ks * 128;

    for (int t = 0; t < TT; t++) {
        const float* __restrict__ hin = g_h[t & 1];

        float zadd[4];
#pragma unroll
        for (int g = 0; g < 4; g++)
            zadd[g] = __ldcs(&g_zx[((size_t)t * GG + g * HH + u) * BB + b]);

        u64 acc[4][4];
#pragma unroll
        for (int i = 0; i < 4; i++)
#pragma unroll
            for (int j = 0; j < 4; j++) acc[i][j] = 0ull;

        float pre[16];
#pragma unroll
        for (int r = 0; r < 16; r++)
            pre[r] = __ldcg(&hin[(kbeg + r) * BB + lane]);

        for (int c8 = 0; c8 < 8; c8++) {
            const int k0 = kbeg + c8 * 16;
#pragma unroll
            for (int r = 0; r < 16; r++)
                myH[r * 32 + lane] = make_float2(pre[r], pre[r]);
            __syncwarp();
            if (c8 < 7) {
#pragma unroll
                for (int r = 0; r < 16; r++)
                    pre[r] = __ldcg(&hin[(k0 + 16 + r) * BB + lane]);
            }
#pragma unroll
            for (int kk = 0; kk < 16; kk++) {
                const u64*       hr = reinterpret_cast<const u64*>(myH + kk * 32);
                const longlong2* wr = reinterpret_cast<const longlong2*>(Wh_s + (k0 + kk) * 32);
                u64 hh[4], ww[4];
#pragma unroll
                for (int i = 0; i < 4; i++) hh[i] = hr[i * 8 + bg];
                longlong2 wa = wr[cg * 2], wb = wr[cg * 2 + 1];
                ww[0] = (u64)wa.x; ww[1] = (u64)wa.y;
                ww[2] = (u64)wb.x; ww[3] = (u64)wb.y;
#pragma unroll
                for (int i = 0; i < 4; i++)
#pragma unroll
                    for (int j = 0; j < 4; j++) ffma2(acc[i][j], hh[i], ww[j]);
            }
            __syncwarp();
        }

#pragma unroll
        for (int j = 0; j < 4; j++) {
            int cl0 = (cg * 4 + j) * 2;
#pragma unroll
            for (int i = 0; i < 4; i++) {
                int    bb = i * 8 + bg;
                float2 v  = f2(acc[i][j]);
                myP[cl0 * 32 + bb]       = v.x;
                myP[(cl0 + 1) * 32 + bb] = v.y;
            }
        }
        __syncthreads();

        float h_new;
        {
            float z[4];
#pragma unroll
            for (int g = 0; g < 4; g++) {
                int   cl = g * 8 + uu;
                float s  = zadd[g];
#pragma unroll
                for (int w = 0; w < 8; w++) s += Pz[w * 1024 + cl * 32 + b];
                z[g] = s;
            }
            float gi = sigmoidf_(z[0]);
            float gf = sigmoidf_(z[1]);
            float gc = tanhf(z[2]);
            float go = sigmoidf_(z[3]);
            c_reg = gf * c_reg + gi * gc;
            h_new = go * tanhf(c_reg);
            g_h[(t + 1) & 1][u * BB + b] = h_new;
        }

        __threadfence();
        __syncthreads();
        if (tid == 0) atomicAdd(&g_bar, 1u);

        if (YMODE == 0) {
            __stcs(&g_y0[((size_t)t * HH + u) * BB + b], h_new);
        } else {
            __stcs(&yout[((size_t)b * TT + t) * HH + u], h_new);
        }
        if (t == TT - 1) {
            hfin[b * HH + u] = h_new;
            cfin[b * HH + u] = c_reg;
        }

        if (tid == 0) {
            const unsigned target = (unsigned)(t + 1) * (unsigned)NBLK;
            while (*((volatile unsigned*)&g_bar) < target) { }
            __threadfence();
        }
        __syncthreads();
    }
}

// ---------------------------------------------------------------------------
// Host launcher (graph-capturable: 9 kernel launches)
// ---------------------------------------------------------------------------
extern "C" void kernel_launch(void* const* d_in, const int* in_sizes, int n_in,
                              void* d_out, int out_size) {
    const float* x    = (const float*)d_in[0];   // [B,T,H]
    const float* Wx   = (const float*)d_in[1];   // [L,H,4H]
    const float* Wh   = (const float*)d_in[2];   // [L,H,4H]
    const float* bias = (const float*)d_in[3];   // [L,4H]

    float* out = (float*)d_out;
    float* y   = out;                               // [B,T,H]
    float* hf  = out + (size_t)BB * TT * HH;        // [L,B,H]
    float* cf  = hf + (size_t)NL * BB * HH;         // [L,B,H]

    const size_t wl = (size_t)HH * GG;

    cudaFuncSetAttribute(lstm_seq<0>, cudaFuncAttributeMaxDynamicSharedMemorySize, SMEM_SEQ);
    cudaFuncSetAttribute(lstm_seq<1>, cudaFuncAttributeMaxDynamicSharedMemorySize, SMEM_SEQ);

    // ---- Layer 0 ----
    zero_state<<<128, 256>>>();
    conv_w<<<dim3(GG / 32, HH / 32, NL), 256>>>(Wx);
    conv_x<<<16384, 256>>>(x);
    gemm_mma<0><<<dim3(32, 128), 256>>>(bias);
    lstm_seq<0><<<NBLK, NTHR, SMEM_SEQ>>>(Wh, nullptr, hf, cf);

    // ---- Layer 1 ----
    zero_state<<<128, 256>>>();
    conv_y0<<<dim3(TT, 8), 256>>>();
    gemm_mma<1><<<dim3(32, 128), 256>>>(bias + GG);
    lstm_seq<1><<<NBLK, NTHR, SMEM_SEQ>>>(Wh + wl, y, hf + BB * HH, cf + BB * HH);
}